// round 6
// baseline (speedup 1.0000x reference)
#include <cuda_runtime.h>
#include <math.h>

// LIF_R one step. Hot loop: I = w @ g + x_in, w = [N,N] fp32 row-major (256 MB).
// out[0:N] = v_new, out[N:2N] = sigmoid(v_next - theta_s).
//
// Strategy: 1 warp per row, 8 rows per 256-thread CTA, g staged once in smem.
// Dot product restructured into batches of 8 independent LDG.128 per warp to
// maximize memory-level parallelism (latency-limited at 53% DRAM otherwise).

#define THREADS 256
#define WARPS_PER_BLOCK 8   // rows per block
#define BATCH 8             // independent LDG.128 per warp per outer iteration

__constant__ float c_R_I     = 18.0f;
__constant__ float c_F_V     = 0.12f;
__constant__ float c_DELTA_V = 12.0f;

__global__ __launch_bounds__(THREADS, 7)
void lif_r_kernel(const float* __restrict__ x_in,
                  const float* __restrict__ v,
                  const float* __restrict__ g,
                  const float* __restrict__ theta_s,
                  const float* __restrict__ w,
                  const float* __restrict__ E_L,
                  const float* __restrict__ C_m,
                  const float* __restrict__ G,
                  const float* __restrict__ tau_g,
                  float* __restrict__ out,
                  int n)
{
    extern __shared__ float sg[];            // n floats (32 KB for N=8192)
    const int tid = threadIdx.x;

    // Stage g into shared memory (vectorized, coalesced).
    const int n4 = n >> 2;                   // 2048 float4 per row
    const float4* __restrict__ g4 = reinterpret_cast<const float4*>(g);
    float4* sg4 = reinterpret_cast<float4*>(sg);
    for (int i = tid; i < n4; i += THREADS) sg4[i] = g4[i];
    __syncthreads();

    const int warp = tid >> 5;
    const int lane = tid & 31;
    const int row  = blockIdx.x * WARPS_PER_BLOCK + warp;
    if (row >= n) return;

    const float4* __restrict__ wrow =
        reinterpret_cast<const float4*>(w + (size_t)row * (size_t)n);

    // Independent accumulators break FMA dependency chains.
    float acc_arr[BATCH];
    #pragma unroll
    for (int j = 0; j < BATCH; j++) acc_arr[j] = 0.f;

    // n4 = 2048 → outer loop runs n4 / (BATCH*32) = 8 iterations.
    const int step = BATCH * 32;
    for (int c0 = lane; c0 < n4; c0 += step) {
        float4 wv[BATCH];
        float4 gv[BATCH];
        // Front-batch the 8 global loads (independent addresses, evict-first:
        // w is stream-once and must not thrash L2).
        #pragma unroll
        for (int j = 0; j < BATCH; j++)
            wv[j] = __ldcs(&wrow[c0 + j * 32]);
        #pragma unroll
        for (int j = 0; j < BATCH; j++)
            gv[j] = sg4[c0 + j * 32];
        #pragma unroll
        for (int j = 0; j < BATCH; j++) {
            acc_arr[j] += fmaf(wv[j].x, gv[j].x,
                          fmaf(wv[j].y, gv[j].y,
                          fmaf(wv[j].z, gv[j].z,
                               wv[j].w * gv[j].w)));
        }
    }
    float acc = ((acc_arr[0] + acc_arr[1]) + (acc_arr[2] + acc_arr[3]))
              + ((acc_arr[4] + acc_arr[5]) + (acc_arr[6] + acc_arr[7]));

    // Warp reduction.
    #pragma unroll
    for (int off = 16; off > 0; off >>= 1)
        acc += __shfl_xor_sync(0xffffffffu, acc, off);

    if (lane == 0) {
        const float vi   = v[row];
        const float th   = theta_s[row];
        const float el   = E_L[row];
        const float gi   = G[row];
        const float cm   = C_m[row];

        const float I      = acc + x_in[row];
        const float dv     = (gi * (el - vi) + I * c_R_I) / cm;
        const float v_next = vi + dv;

        const float s_soft = 1.0f / (1.0f + __expf(-(v_next - th)));

        const float spiked  = (v_next >= th) ? 1.0f : 0.0f;
        const float v_reset = el + c_F_V * (vi - el) - c_DELTA_V;
        const float v_new   = spiked * v_reset + (1.0f - spiked) * v_next;

        out[row]     = v_new;
        out[n + row] = s_soft;
    }
}

extern "C" void kernel_launch(void* const* d_in, const int* in_sizes, int n_in,
                              void* d_out, int out_size)
{
    // metadata order: x_in, v, g, theta_s, w, E_L, C_m, G, tau_g
    const float* x_in    = (const float*)d_in[0];
    const float* v       = (const float*)d_in[1];
    const float* g       = (const float*)d_in[2];
    const float* theta_s = (const float*)d_in[3];
    const float* w       = (const float*)d_in[4];
    const float* E_L     = (const float*)d_in[5];
    const float* C_m     = (const float*)d_in[6];
    const float* G       = (const float*)d_in[7];
    const float* tau_g   = (const float*)d_in[8];
    float* out = (float*)d_out;

    const int n = in_sizes[0];
    const int blocks = (n + WARPS_PER_BLOCK - 1) / WARPS_PER_BLOCK;
    const size_t smem = (size_t)n * sizeof(float);

    lif_r_kernel<<<blocks, THREADS, smem>>>(x_in, v, g, theta_s, w,
                                            E_L, C_m, G, tau_g, out, n);
}

// round 10
// speedup vs baseline: 1.2137x; 1.2137x over previous
#include <cuda_runtime.h>
#include <cuda.h>
#include <math.h>
#include <stdint.h>

// LIF_R one step. Hot loop: I = w @ g + x_in, w = [N,N] fp32 row-major (256 MB).
// out[0:N] = v_new, out[N:2N] = sigmoid(v_next - theta_s).
//
// LDG path plateaus ~4 TB/s (per-SM outstanding-miss ceiling; confirmed across
// two different LDG schedules). Switch the w stream to cp.async.bulk (UBLKCP)
// quad-buffered into smem: persistent CTAs (1/SM), 8 consumer warps + 1
// producer warp, 4-stage pipeline of 8x4KB row chunks with mbarrier expect_tx.
// 128KB in flight per SM.

#define CONSUMER_WARPS 8
#define THREADS (CONSUMER_WARPS * 32 + 32)   // 288: warps 0-7 consume, warp 8 produces
#define CHUNK_F   1024                        // floats per row-chunk (4 KB)
#define CHUNK_B   4096
#define ROWS_PB   8                           // rows per row-block (one per consumer warp)
#define STAGES    4
#define STAGE_F   (ROWS_PB * CHUNK_F)         // 8192 floats = 32 KB per stage

__constant__ float c_R_I     = 18.0f;
__constant__ float c_F_V     = 0.12f;
__constant__ float c_DELTA_V = 12.0f;

__device__ __forceinline__ uint32_t smem_u32(const void* p) {
    return (uint32_t)__cvta_generic_to_shared(p);
}
__device__ __forceinline__ void mbar_init(uint32_t mbar, uint32_t count) {
    asm volatile("mbarrier.init.shared.b64 [%0], %1;" :: "r"(mbar), "r"(count) : "memory");
}
__device__ __forceinline__ void mbar_expect_tx(uint32_t mbar, uint32_t bytes) {
    asm volatile("mbarrier.arrive.expect_tx.shared.b64 _, [%0], %1;"
                 :: "r"(mbar), "r"(bytes) : "memory");
}
__device__ __forceinline__ void mbar_arrive(uint32_t mbar) {
    asm volatile("mbarrier.arrive.shared.b64 _, [%0];" :: "r"(mbar) : "memory");
}
// acquire wait: consumers do generic LDS after this
__device__ __forceinline__ void mbar_wait_acq(uint32_t mbar, uint32_t parity) {
    asm volatile(
        "{\n\t.reg .pred P;\n\t"
        "WAIT_%=:\n\t"
        "mbarrier.try_wait.parity.acquire.cta.shared::cta.b64 P, [%0], %1, 0x989680;\n\t"
        "@P bra.uni DONE_%=;\n\t"
        "bra.uni WAIT_%=;\n\t"
        "DONE_%=:\n\t}"
        :: "r"(mbar), "r"(parity) : "memory");
}
// relaxed wait: producer's post-wait accesses are async-proxy bulk copies only
__device__ __forceinline__ void mbar_wait_rlx(uint32_t mbar, uint32_t parity) {
    asm volatile(
        "{\n\t.reg .pred P;\n\t"
        "WAIT_%=:\n\t"
        "mbarrier.try_wait.parity.relaxed.cta.shared::cta.b64 P, [%0], %1, 0x989680;\n\t"
        "@P bra.uni DONE_%=;\n\t"
        "bra.uni WAIT_%=;\n\t"
        "DONE_%=:\n\t}"
        :: "r"(mbar), "r"(parity) : "memory");
}
__device__ __forceinline__ void bulk_copy(uint32_t dst_smem, const void* src_gmem,
                                          uint32_t bytes, uint32_t mbar) {
    asm volatile(
        "cp.async.bulk.shared::cta.global.mbarrier::complete_tx::bytes [%0], [%1], %2, [%3];"
        :: "r"(dst_smem), "l"(src_gmem), "r"(bytes), "r"(mbar) : "memory");
}

__global__ __launch_bounds__(THREADS, 1)
void lif_r_tma_kernel(const float* __restrict__ x_in,
                      const float* __restrict__ v,
                      const float* __restrict__ g,
                      const float* __restrict__ theta_s,
                      const float* __restrict__ w,
                      const float* __restrict__ E_L,
                      const float* __restrict__ C_m,
                      const float* __restrict__ G,
                      float* __restrict__ out,
                      int n)
{
    extern __shared__ float smem[];
    float* sg = smem;                         // n floats (32 KB)
    float* sw = smem + n;                     // STAGES * STAGE_F floats (128 KB)

    __shared__ __align__(8) uint64_t s_full[STAGES];
    __shared__ __align__(8) uint64_t s_empty[STAGES];

    const int tid  = threadIdx.x;
    const int wid  = tid >> 5;
    const int lane = tid & 31;

    if (tid == 0) {
        #pragma unroll
        for (int s = 0; s < STAGES; s++) {
            mbar_init(smem_u32(&s_full[s]),  1);              // producer expect_tx arrival
            mbar_init(smem_u32(&s_empty[s]), CONSUMER_WARPS); // one elected arrive per warp
        }
    }
    __syncthreads();

    // Stage g once (all 288 threads, coalesced float4).
    const int n4 = n >> 2;
    const float4* __restrict__ g4 = reinterpret_cast<const float4*>(g);
    float4* sg4 = reinterpret_cast<float4*>(sg);
    for (int i = tid; i < n4; i += THREADS) sg4[i] = g4[i];
    __syncthreads();
    // No CTA-wide syncs below this point.

    const int nchunks = n / CHUNK_F;          // 8 for N=8192
    const int nrb     = n / ROWS_PB;          // 1024 row-blocks

    if (wid == CONSUMER_WARPS) {
        // ---- Producer warp: single thread issues the whole pipeline. ----
        if (lane != 0) return;
        int s = 0, ph = 1;                    // phase=1: first empty-wait passes on fresh barrier
        for (int rb = blockIdx.x; rb < nrb; rb += gridDim.x) {
            const size_t row0 = (size_t)rb * ROWS_PB;
            for (int c = 0; c < nchunks; c++) {
                mbar_wait_rlx(smem_u32(&s_empty[s]), (uint32_t)ph);
                const uint32_t full = smem_u32(&s_full[s]);
                mbar_expect_tx(full, ROWS_PB * CHUNK_B);
                const uint32_t dst0 = smem_u32(sw + s * STAGE_F);
                const float* src0 = w + row0 * (size_t)n + (size_t)c * CHUNK_F;
                #pragma unroll
                for (int j = 0; j < ROWS_PB; j++)
                    bulk_copy(dst0 + j * CHUNK_B, src0 + (size_t)j * n, CHUNK_B, full);
                if (++s == STAGES) { s = 0; ph ^= 1; }
            }
        }
        return;
    }

    // ---- Consumer warps: warp wid handles row (rb*8 + wid). ----
    int s = 0, ph = 0;
    for (int rb = blockIdx.x; rb < nrb; rb += gridDim.x) {
        float acc0 = 0.f, acc1 = 0.f;
        for (int c = 0; c < nchunks; c++) {
            mbar_wait_acq(smem_u32(&s_full[s]), (uint32_t)ph);
            const float4* wbuf = reinterpret_cast<const float4*>(sw + s * STAGE_F + wid * CHUNK_F);
            const float4* gbuf = reinterpret_cast<const float4*>(sg + c * CHUNK_F);
            #pragma unroll
            for (int k = 0; k < CHUNK_F / 128; k++) {   // 8 float4 per lane
                float4 wv = wbuf[lane + 32 * k];
                float4 gv = gbuf[lane + 32 * k];
                float t = fmaf(wv.x, gv.x,
                          fmaf(wv.y, gv.y,
                          fmaf(wv.z, gv.z, wv.w * gv.w)));
                if (k & 1) acc1 += t; else acc0 += t;
            }
            __syncwarp();
            if (lane == 0) mbar_arrive(smem_u32(&s_empty[s]));
            if (++s == STAGES) { s = 0; ph ^= 1; }
        }
        float acc = acc0 + acc1;
        #pragma unroll
        for (int off = 16; off > 0; off >>= 1)
            acc += __shfl_xor_sync(0xffffffffu, acc, off);

        if (lane == 0) {
            const int row = rb * ROWS_PB + wid;
            const float vi = v[row];
            const float th = theta_s[row];
            const float el = E_L[row];
            const float gi = G[row];
            const float cm = C_m[row];

            const float I      = acc + x_in[row];
            const float dv     = (gi * (el - vi) + I * c_R_I) / cm;
            const float v_next = vi + dv;
            const float s_soft = 1.0f / (1.0f + __expf(-(v_next - th)));
            const float spiked = (v_next >= th) ? 1.0f : 0.0f;
            const float v_rst  = el + c_F_V * (vi - el) - c_DELTA_V;
            const float v_new  = spiked * v_rst + (1.0f - spiked) * v_next;

            out[row]     = v_new;
            out[n + row] = s_soft;
        }
    }
}

extern "C" void kernel_launch(void* const* d_in, const int* in_sizes, int n_in,
                              void* d_out, int out_size)
{
    // metadata order: x_in, v, g, theta_s, w, E_L, C_m, G, tau_g
    const float* x_in    = (const float*)d_in[0];
    const float* v       = (const float*)d_in[1];
    const float* g       = (const float*)d_in[2];
    const float* theta_s = (const float*)d_in[3];
    const float* w       = (const float*)d_in[4];
    const float* E_L     = (const float*)d_in[5];
    const float* C_m     = (const float*)d_in[6];
    const float* G       = (const float*)d_in[7];
    float* out = (float*)d_out;

    const int n = in_sizes[0];

    int nsm = 0;
    cudaDeviceGetAttribute(&nsm, cudaDevAttrMultiProcessorCount, 0);
    if (nsm <= 0) nsm = 148;

    const size_t smem = (size_t)n * sizeof(float) +
                        (size_t)STAGES * STAGE_F * sizeof(float);   // 160 KB for N=8192
    cudaFuncSetAttribute(lif_r_tma_kernel,
                         cudaFuncAttributeMaxDynamicSharedMemorySize, (int)smem);

    lif_r_tma_kernel<<<nsm, THREADS, smem>>>(x_in, v, g, theta_s, w,
                                             E_L, C_m, G, out, n);
}

// round 17
// speedup vs baseline: 1.3703x; 1.1290x over previous
#include <cuda_runtime.h>
#include <cuda.h>
#include <math.h>
#include <stdint.h>

// LIF_R one step. Hot loop: I = w @ g + x_in, w = [N,N] fp32 row-major (256 MB).
// out[0:N] = v_new, out[N:2N] = sigmoid(v_next - theta_s).
//
// TMA bulk pipeline confirmed (53.8us, DRAM 64%). Residual = lockstep
// bubbles (all consumers wait on the same stage). Split into 2 CTAs/SM, each
// with its own 4-stage pipeline (4 consumer warps + 1 producer, 16KB stages,
// 96KB smem/CTA) -> two desynchronized pipelines per SM hide each other's
// wait/burst phases. Same 128KB bulk in-flight per SM.

#define CONSUMER_WARPS 4
#define THREADS (CONSUMER_WARPS * 32 + 32)   // 160: warps 0-3 consume, warp 4 produces
#define CHUNK_F   1024                        // floats per row-chunk (4 KB)
#define CHUNK_B   4096
#define ROWS_PB   4                           // rows per row-block (one per consumer warp)
#define STAGES    4
#define STAGE_F   (ROWS_PB * CHUNK_F)         // 4096 floats = 16 KB per stage

__constant__ float c_R_I     = 18.0f;
__constant__ float c_F_V     = 0.12f;
__constant__ float c_DELTA_V = 12.0f;

__device__ __forceinline__ uint32_t smem_u32(const void* p) {
    return (uint32_t)__cvta_generic_to_shared(p);
}
__device__ __forceinline__ void mbar_init(uint32_t mbar, uint32_t count) {
    asm volatile("mbarrier.init.shared.b64 [%0], %1;" :: "r"(mbar), "r"(count) : "memory");
}
__device__ __forceinline__ void mbar_expect_tx(uint32_t mbar, uint32_t bytes) {
    asm volatile("mbarrier.arrive.expect_tx.shared.b64 _, [%0], %1;"
                 :: "r"(mbar), "r"(bytes) : "memory");
}
__device__ __forceinline__ void mbar_arrive(uint32_t mbar) {
    asm volatile("mbarrier.arrive.shared.b64 _, [%0];" :: "r"(mbar) : "memory");
}
// acquire wait: consumers do generic LDS after this
__device__ __forceinline__ void mbar_wait_acq(uint32_t mbar, uint32_t parity) {
    asm volatile(
        "{\n\t.reg .pred P;\n\t"
        "WAIT_%=:\n\t"
        "mbarrier.try_wait.parity.acquire.cta.shared::cta.b64 P, [%0], %1, 0x989680;\n\t"
        "@P bra.uni DONE_%=;\n\t"
        "bra.uni WAIT_%=;\n\t"
        "DONE_%=:\n\t}"
        :: "r"(mbar), "r"(parity) : "memory");
}
// relaxed wait: producer's post-wait accesses are async-proxy bulk copies only
__device__ __forceinline__ void mbar_wait_rlx(uint32_t mbar, uint32_t parity) {
    asm volatile(
        "{\n\t.reg .pred P;\n\t"
        "WAIT_%=:\n\t"
        "mbarrier.try_wait.parity.relaxed.cta.shared::cta.b64 P, [%0], %1, 0x989680;\n\t"
        "@P bra.uni DONE_%=;\n\t"
        "bra.uni WAIT_%=;\n\t"
        "DONE_%=:\n\t}"
        :: "r"(mbar), "r"(parity) : "memory");
}
__device__ __forceinline__ void bulk_copy(uint32_t dst_smem, const void* src_gmem,
                                          uint32_t bytes, uint32_t mbar) {
    asm volatile(
        "cp.async.bulk.shared::cta.global.mbarrier::complete_tx::bytes [%0], [%1], %2, [%3];"
        :: "r"(dst_smem), "l"(src_gmem), "r"(bytes), "r"(mbar) : "memory");
}

__global__ __launch_bounds__(THREADS, 2)
void lif_r_tma_kernel(const float* __restrict__ x_in,
                      const float* __restrict__ v,
                      const float* __restrict__ g,
                      const float* __restrict__ theta_s,
                      const float* __restrict__ w,
                      const float* __restrict__ E_L,
                      const float* __restrict__ C_m,
                      const float* __restrict__ G,
                      float* __restrict__ out,
                      int n)
{
    extern __shared__ float smem[];
    float* sg = smem;                         // n floats (32 KB)
    float* sw = smem + n;                     // STAGES * STAGE_F floats (64 KB)

    __shared__ __align__(8) uint64_t s_full[STAGES];
    __shared__ __align__(8) uint64_t s_empty[STAGES];

    const int tid  = threadIdx.x;
    const int wid  = tid >> 5;
    const int lane = tid & 31;

    if (tid == 0) {
        #pragma unroll
        for (int s = 0; s < STAGES; s++) {
            mbar_init(smem_u32(&s_full[s]),  1);              // producer expect_tx arrival
            mbar_init(smem_u32(&s_empty[s]), CONSUMER_WARPS); // one elected arrive per warp
        }
    }
    __syncthreads();

    // Stage g once (all 160 threads, coalesced float4).
    const int n4 = n >> 2;
    const float4* __restrict__ g4 = reinterpret_cast<const float4*>(g);
    float4* sg4 = reinterpret_cast<float4*>(sg);
    for (int i = tid; i < n4; i += THREADS) sg4[i] = g4[i];
    __syncthreads();
    // No CTA-wide syncs below this point.

    const int nchunks = n / CHUNK_F;          // 8 for N=8192
    const int nrb     = n / ROWS_PB;          // 2048 row-blocks

    if (wid == CONSUMER_WARPS) {
        // ---- Producer warp: single thread issues the whole pipeline. ----
        if (lane != 0) return;
        int s = 0, ph = 1;                    // phase=1: first empty-wait passes on fresh barrier
        for (int rb = blockIdx.x; rb < nrb; rb += gridDim.x) {
            const size_t row0 = (size_t)rb * ROWS_PB;
            for (int c = 0; c < nchunks; c++) {
                mbar_wait_rlx(smem_u32(&s_empty[s]), (uint32_t)ph);
                const uint32_t full = smem_u32(&s_full[s]);
                mbar_expect_tx(full, ROWS_PB * CHUNK_B);
                const uint32_t dst0 = smem_u32(sw + s * STAGE_F);
                const float* src0 = w + row0 * (size_t)n + (size_t)c * CHUNK_F;
                #pragma unroll
                for (int j = 0; j < ROWS_PB; j++)
                    bulk_copy(dst0 + j * CHUNK_B, src0 + (size_t)j * n, CHUNK_B, full);
                if (++s == STAGES) { s = 0; ph ^= 1; }
            }
        }
        return;
    }

    // ---- Consumer warps: warp wid handles row (rb*4 + wid). ----
    int s = 0, ph = 0;
    for (int rb = blockIdx.x; rb < nrb; rb += gridDim.x) {
        float acc0 = 0.f, acc1 = 0.f;
        for (int c = 0; c < nchunks; c++) {
            mbar_wait_acq(smem_u32(&s_full[s]), (uint32_t)ph);
            const float4* wbuf = reinterpret_cast<const float4*>(sw + s * STAGE_F + wid * CHUNK_F);
            const float4* gbuf = reinterpret_cast<const float4*>(sg + c * CHUNK_F);
            #pragma unroll
            for (int k = 0; k < CHUNK_F / 128; k++) {   // 8 float4 per lane
                float4 wv = wbuf[lane + 32 * k];
                float4 gv = gbuf[lane + 32 * k];
                float t = fmaf(wv.x, gv.x,
                          fmaf(wv.y, gv.y,
                          fmaf(wv.z, gv.z, wv.w * gv.w)));
                if (k & 1) acc1 += t; else acc0 += t;
            }
            __syncwarp();
            if (lane == 0) mbar_arrive(smem_u32(&s_empty[s]));
            if (++s == STAGES) { s = 0; ph ^= 1; }
        }
        float acc = acc0 + acc1;
        #pragma unroll
        for (int off = 16; off > 0; off >>= 1)
            acc += __shfl_xor_sync(0xffffffffu, acc, off);

        if (lane == 0) {
            const int row = rb * ROWS_PB + wid;
            const float vi = v[row];
            const float th = theta_s[row];
            const float el = E_L[row];
            const float gi = G[row];
            const float cm = C_m[row];

            const float I      = acc + x_in[row];
            const float dv     = (gi * (el - vi) + I * c_R_I) / cm;
            const float v_next = vi + dv;
            const float s_soft = 1.0f / (1.0f + __expf(-(v_next - th)));
            const float spiked = (v_next >= th) ? 1.0f : 0.0f;
            const float v_rst  = el + c_F_V * (vi - el) - c_DELTA_V;
            const float v_new  = spiked * v_rst + (1.0f - spiked) * v_next;

            out[row]     = v_new;
            out[n + row] = s_soft;
        }
    }
}

extern "C" void kernel_launch(void* const* d_in, const int* in_sizes, int n_in,
                              void* d_out, int out_size)
{
    // metadata order: x_in, v, g, theta_s, w, E_L, C_m, G, tau_g
    const float* x_in    = (const float*)d_in[0];
    const float* v       = (const float*)d_in[1];
    const float* g       = (const float*)d_in[2];
    const float* theta_s = (const float*)d_in[3];
    const float* w       = (const float*)d_in[4];
    const float* E_L     = (const float*)d_in[5];
    const float* C_m     = (const float*)d_in[6];
    const float* G       = (const float*)d_in[7];
    float* out = (float*)d_out;

    const int n = in_sizes[0];

    int nsm = 0;
    cudaDeviceGetAttribute(&nsm, cudaDevAttrMultiProcessorCount, 0);
    if (nsm <= 0) nsm = 148;

    const size_t smem = (size_t)n * sizeof(float) +
                        (size_t)STAGES * STAGE_F * sizeof(float);   // 96 KB for N=8192
    cudaFuncSetAttribute(lif_r_tma_kernel,
                         cudaFuncAttributeMaxDynamicSharedMemorySize, (int)smem);

    lif_r_tma_kernel<<<2 * nsm, THREADS, smem>>>(x_in, v, g, theta_s, w,
                                                 E_L, C_m, G, out, n);
}